// round 14
// baseline (speedup 1.0000x reference)
#include <cuda_runtime.h>
#include <cuda_bf16.h>
#include <cuda_fp16.h>
#include <cstdint>

#define NN 50000
#define NE 800000
#define DD 128
#define BN_EPS 1e-5f
#define WSTRIDE 136
#define WTILE_BYTES (DD * WSTRIDE * 2)
#define WHALF_BYTES (64 * WSTRIDE * 2)

// ---- static device scratch ----
__device__ __align__(16) __half g_h16[NN * DD];
__device__ float g_agg[NN * DD];
__device__ int   g_deg[NN];
__device__ float g_dinv[NN];
__device__ int   g_rowstart[NN];
__device__ int   g_cursor[NN];
__device__ int4  g_nodeinfo[NN];      // (rowstart, deg, dinv_bits, 0)
__device__ int2  g_csre[NE];
__device__ float g_stats[4 * DD];
__device__ unsigned long long g_sstate[200];
__device__ unsigned int g_sctr;
__device__ __align__(16) unsigned short g_w1h[DD * WSTRIDE];
__device__ __align__(16) unsigned short g_w1l[DD * WSTRIDE];
__device__ __align__(16) unsigned short g_w2h[DD * WSTRIDE];
__device__ __align__(16) unsigned short g_w2l[DD * WSTRIDE];

// ================= helpers =================
__device__ __forceinline__ uint32_t smem_u32(const void* p) {
    uint32_t a;
    asm("{ .reg .u64 t; cvta.to.shared.u64 t, %1; cvt.u32.u64 %0, t; }"
        : "=r"(a) : "l"(p));
    return a;
}
__device__ __forceinline__ void ldsm4(uint32_t& r0, uint32_t& r1,
                                      uint32_t& r2, uint32_t& r3, uint32_t addr) {
    asm volatile("ldmatrix.sync.aligned.m8n8.x4.shared.b16 {%0,%1,%2,%3}, [%4];"
                 : "=r"(r0), "=r"(r1), "=r"(r2), "=r"(r3) : "r"(addr));
}
__device__ __forceinline__ void mma16816(float* c, uint32_t a0, uint32_t a1,
                                         uint32_t a2, uint32_t a3,
                                         uint32_t b0, uint32_t b1) {
    asm volatile("mma.sync.aligned.m16n8k16.row.col.f32.bf16.bf16.f32 "
                 "{%0,%1,%2,%3}, {%4,%5,%6,%7}, {%8,%9}, {%0,%1,%2,%3};"
                 : "+f"(c[0]), "+f"(c[1]), "+f"(c[2]), "+f"(c[3])
                 : "r"(a0), "r"(a1), "r"(a2), "r"(a3), "r"(b0), "r"(b1));
}
__device__ __forceinline__ unsigned short bf_hi(float x) {
    __nv_bfloat16 b = __float2bfloat16(x);
    return *reinterpret_cast<unsigned short*>(&b);
}
__device__ __forceinline__ float bf_val(unsigned short u) {
    __nv_bfloat16 b = *reinterpret_cast<__nv_bfloat16*>(&u);
    return __bfloat162float(b);
}

// ================= W prepack + per-call zeroing =================
__global__ void k_wprep(const float* __restrict__ W1, const float* __restrict__ W2) {
    int i = blockIdx.x * 256 + threadIdx.x;  // 32768 threads
    if (i < NN) g_deg[i] = 0;
    {
        int i2 = i + 32768;
        if (i2 < NN) g_deg[i2] = 0;
    }
    if (i < 4 * DD) g_stats[i] = 0.f;
    if (i < 200) g_sstate[i] = 0ULL;
    if (i == 0) g_sctr = 0u;
    if (i < 2 * DD * DD) {
        int layer = i >> 14;
        int idx = i & (DD * DD - 1);
        int k = idx >> 7, n = idx & 127;
        float w = (layer ? W2 : W1)[idx];
        unsigned short h = bf_hi(w);
        unsigned short l = bf_hi(w - bf_val(h));
        int o = n * WSTRIDE + k;
        if (layer) { g_w2h[o] = h; g_w2l[o] = l; }
        else       { g_w1h[o] = h; g_w1l[o] = l; }
    }
}

// ================= degree count =================
__global__ void k_deg(const int* __restrict__ dst) {
    int t = blockIdx.x * 256 + threadIdx.x;
    if (t * 4 < NE) {
        int4 d = ((const int4*)dst)[t];
        atomicAdd(&g_deg[d.x], 1);
        atomicAdd(&g_deg[d.y], 1);
        atomicAdd(&g_deg[d.z], 1);
        atomicAdd(&g_deg[d.w], 1);
    }
}

// ================= single-kernel decoupled-lookback scan =================
__global__ void k_scan() {
    __shared__ int wsum[8];
    __shared__ int s_bid, s_total, s_prefix;
    int tid = threadIdx.x;
    if (tid == 0) s_bid = (int)atomicAdd(&g_sctr, 1u);
    __syncthreads();
    int bid = s_bid;
    int i = bid * 256 + tid;
    int d0 = (i < NN) ? g_deg[i] : 0;
    int v = d0;
    int lane = tid & 31, wid = tid >> 5;
#pragma unroll
    for (int o = 1; o < 32; o <<= 1) {
        int n = __shfl_up_sync(0xffffffffu, v, o);
        if (lane >= o) v += n;
    }
    if (lane == 31) wsum[wid] = v;
    __syncthreads();
    if (wid == 0) {
        int s = (lane < 8) ? wsum[lane] : 0;
#pragma unroll
        for (int o = 1; o < 8; o <<= 1) {
            int n = __shfl_up_sync(0xffffffffu, s, o);
            if (lane >= o) s += n;
        }
        if (lane < 8) wsum[lane] = s;
    }
    __syncthreads();
    int off = (wid > 0) ? wsum[wid - 1] : 0;
    int incl = v + off;
    if (tid == 255) {
        s_total = incl;
        if (bid == 0) atomicExch(&g_sstate[0], (2ULL << 32) | (unsigned)incl);
        else          atomicExch(&g_sstate[bid], (1ULL << 32) | (unsigned)incl);
    }
    __syncthreads();
    if (tid == 0) {
        int pre = 0;
        if (bid > 0) {
            int j = bid - 1;
            for (;;) {
                unsigned long long s;
                do { s = atomicAdd(&g_sstate[j], 0ULL); } while ((s >> 32) == 0ULL);
                pre += (int)(s & 0xffffffffULL);
                if ((s >> 32) == 2ULL) break;
                j--;
            }
            atomicExch(&g_sstate[bid], (2ULL << 32) | (unsigned)(pre + s_total));
        }
        s_prefix = pre;
    }
    __syncthreads();
    if (i < NN) {
        int rs = s_prefix + incl - d0;
        float di = rsqrtf((float)(d0 + 1));
        g_rowstart[i] = rs;
        g_cursor[i] = rs;
        g_dinv[i] = di;
        g_nodeinfo[i] = make_int4(rs, d0, __float_as_int(di), 0);
    }
}

// ================= CSR fill =================
__global__ void k_csr(const int* __restrict__ src, const int* __restrict__ dst) {
    int e = blockIdx.x * 256 + threadIdx.x;
    if (e < NE) {
        int s = src[e], d = dst[e];
        int pos = atomicAdd(&g_cursor[d], 1);
        float w = g_dinv[s] * g_dinv[d];
        g_csre[pos] = make_int2(s, __float_as_int(w));
    }
}

// ================= bf16 mma GEMM: 128 rows x 64 cols per block =================
#define XH_OFF 0
#define XL_OFF WTILE_BYTES
#define WH_OFF (2 * WTILE_BYTES)
#define WL_OFF (2 * WTILE_BYTES + WHALF_BYTES)
#define SMEM_MMA (2 * WTILE_BYTES + 2 * WHALF_BYTES)

__global__ void __launch_bounds__(256, 2) k_gemm_mma(
        const float* __restrict__ Xin,
        const unsigned short* __restrict__ Wh, const unsigned short* __restrict__ Wl,
        const float* __restrict__ gamma, const float* __restrict__ beta,
        const float* __restrict__ aparam, int bn_off, int use_agg) {
    extern __shared__ char sm[];
    __shared__ float s_scale[DD];
    __shared__ float s_shift[DD];

    int tid = threadIdx.x;
    int wid = tid >> 5, lane = tid & 31;
    int row0 = (blockIdx.x >> 1) * 128;
    int nh = blockIdx.x & 1;
    const float* X = use_agg ? (const float*)g_agg : Xin;

    float alpha = 0.f;
    if (bn_off >= 0) {
        alpha = aparam[0];
        if (tid < DD) {
            float mu  = g_stats[bn_off + tid] * (1.f / NN);
            float var = g_stats[bn_off + DD + tid] * (1.f / NN) - mu * mu;
            float sc  = gamma[tid] * rsqrtf(var + BN_EPS);
            s_scale[tid] = sc;
            s_shift[tid] = beta[tid] - mu * sc;
        }
    }

    {
        const float4* sh = (const float4*)(Wh + nh * 64 * WSTRIDE);
        const float4* sl = (const float4*)(Wl + nh * 64 * WSTRIDE);
        float4* dh = (float4*)(sm + WH_OFF);
        float4* dl = (float4*)(sm + WL_OFF);
#pragma unroll 4
        for (int i = tid; i < WHALF_BYTES / 16; i += 256) { dh[i] = sh[i]; dl[i] = sl[i]; }
    }
    __syncthreads();

    {
        const float4* X4 = (const float4*)X;
#pragma unroll 4
        for (int i = tid; i < 128 * 32; i += 256) {
            int r = i >> 5, c = i & 31;
            int gr = row0 + r;
            float4 v = make_float4(0.f, 0.f, 0.f, 0.f);
            if (gr < NN) v = X4[gr * 32 + c];
            if (bn_off >= 0) {
                int cc = c * 4;
                float y;
                y = v.x * s_scale[cc]     + s_shift[cc];     v.x = (y >= 0.f) ? y : alpha * y;
                y = v.y * s_scale[cc + 1] + s_shift[cc + 1]; v.y = (y >= 0.f) ? y : alpha * y;
                y = v.z * s_scale[cc + 2] + s_shift[cc + 2]; v.z = (y >= 0.f) ? y : alpha * y;
                y = v.w * s_scale[cc + 3] + s_shift[cc + 3]; v.w = (y >= 0.f) ? y : alpha * y;
            }
            unsigned short h0 = bf_hi(v.x), h1 = bf_hi(v.y), h2 = bf_hi(v.z), h3 = bf_hi(v.w);
            unsigned short l0 = bf_hi(v.x - bf_val(h0));
            unsigned short l1 = bf_hi(v.y - bf_val(h1));
            unsigned short l2 = bf_hi(v.z - bf_val(h2));
            unsigned short l3 = bf_hi(v.w - bf_val(h3));
            int o = r * (WSTRIDE * 2) + c * 8;
            *(uint2*)(sm + XH_OFF + o) = make_uint2((uint32_t)h0 | ((uint32_t)h1 << 16),
                                                    (uint32_t)h2 | ((uint32_t)h3 << 16));
            *(uint2*)(sm + XL_OFF + o) = make_uint2((uint32_t)l0 | ((uint32_t)l1 << 16),
                                                    (uint32_t)l2 | ((uint32_t)l3 << 16));
        }
    }
    __syncthreads();

    int wrow0 = wid * 16;
    uint32_t base = smem_u32(sm);
    uint32_t a_h = base + XH_OFF + (wrow0 + (lane & 15)) * (WSTRIDE * 2) + (lane >> 4) * 16;
    uint32_t a_l = a_h + (XL_OFF - XH_OFF);
    uint32_t b_h = base + WH_OFF + ((lane >> 4) * 8 + (lane & 7)) * (WSTRIDE * 2)
                 + ((lane >> 3) & 1) * 16;
    uint32_t b_l = b_h + (WL_OFF - WH_OFF);

    float acc[8][4];
#pragma unroll
    for (int nt = 0; nt < 8; nt++)
#pragma unroll
        for (int j = 0; j < 4; j++) acc[nt][j] = 0.f;

#pragma unroll 1
    for (int p = 0; p < 3; p++) {
        uint32_t aa = (p == 2) ? a_l : a_h;
        uint32_t bb = (p == 1) ? b_l : b_h;
#pragma unroll 1
        for (int k = 0; k < 8; k++) {
            uint32_t a0, a1, a2, a3;
            ldsm4(a0, a1, a2, a3, aa + k * 32);
#pragma unroll
            for (int ntp = 0; ntp < 4; ntp++) {
                uint32_t b0, b1, b2, b3;
                ldsm4(b0, b1, b2, b3, bb + k * 32 + ntp * 16 * (WSTRIDE * 2));
                mma16816(acc[2 * ntp],     a0, a1, a2, a3, b0, b1);
                mma16816(acc[2 * ntp + 1], a0, a1, a2, a3, b2, b3);
            }
        }
    }

    int g = lane >> 2, t = lane & 3;
    int r1 = row0 + wrow0 + g;
    int r2 = r1 + 8;
#pragma unroll
    for (int nt = 0; nt < 8; nt++) {
        int col = nh * 64 + nt * 8 + t * 2;
        if (r1 < NN)
            *(__half2*)(g_h16 + (size_t)r1 * DD + col) =
                __floats2half2_rn(acc[nt][0], acc[nt][1]);
        if (r2 < NN)
            *(__half2*)(g_h16 + (size_t)r2 * DD + col) =
                __floats2half2_rn(acc[nt][2], acc[nt][3]);
    }
}

// ================= CSR aggregation: 2 warps per node, 8-wide masked groups =================
__global__ void __launch_bounds__(256) k_agg(const float* __restrict__ bias, int soff) {
    __shared__ float s_part[4][DD];
    __shared__ float s_sum[DD];
    __shared__ float s_sq[DD];
    int tid = threadIdx.x;
    if (tid < DD) { s_sum[tid] = 0.f; s_sq[tid] = 0.f; }

    int pair = tid >> 6;           // 0..3 (node within block)
    int wp   = (tid >> 5) & 1;     // warp-in-pair
    int lane = tid & 31;
    int node = blockIdx.x * 4 + pair;
    bool valid = node < NN;

    float4 acc = make_float4(0.f, 0.f, 0.f, 0.f);
    if (valid) {
        const uint2* h2 = (const uint2*)g_h16;
        int4 ni = __ldg(&g_nodeinfo[node]);
        int base = ni.x;
        int cnt  = ni.y;
        float di = __int_as_float(ni.z);

        if (wp == 0) {
            float w0 = di * di;
            uint2 sr = __ldg(&h2[node * 32 + lane]);
            float2 s01 = __half22float2(*(__half2*)&sr.x);
            float2 s23 = __half22float2(*(__half2*)&sr.y);
            float4 bv = __ldg(&((const float4*)bias)[lane]);
            acc.x = s01.x * w0 + bv.x;
            acc.y = s01.y * w0 + bv.y;
            acc.z = s23.x * w0 + bv.z;
            acc.w = s23.y * w0 + bv.w;
        }

        int mid = cnt >> 1;
        int js = wp ? mid : 0;
        int je = wp ? cnt : mid;
        const int2* ep = g_csre + base;
#pragma unroll 1
        for (int j0 = js; j0 < je; j0 += 8) {
            int2 e[8];
#pragma unroll
            for (int u = 0; u < 8; u++)
                e[u] = (j0 + u < je) ? __ldg(ep + j0 + u) : make_int2(node, 0);
            uint2 r[8];
#pragma unroll
            for (int u = 0; u < 8; u++) r[u] = __ldg(&h2[e[u].x * 32 + lane]);
#pragma unroll
            for (int u = 0; u < 8; u++) {
                float wf = __int_as_float(e[u].y);
                float2 f01 = __half22float2(*(__half2*)&r[u].x);
                float2 f23 = __half22float2(*(__half2*)&r[u].y);
                acc.x += f01.x * wf;
                acc.y += f01.y * wf;
                acc.z += f23.x * wf;
                acc.w += f23.y * wf;
            }
        }
    }

    // partner warp deposits its partial
    if (wp == 1) {
        s_part[pair][lane * 4]     = acc.x;
        s_part[pair][lane * 4 + 1] = acc.y;
        s_part[pair][lane * 4 + 2] = acc.z;
        s_part[pair][lane * 4 + 3] = acc.w;
    }
    __syncthreads();

    if (wp == 0 && valid) {
        acc.x += s_part[pair][lane * 4];
        acc.y += s_part[pair][lane * 4 + 1];
        acc.z += s_part[pair][lane * 4 + 2];
        acc.w += s_part[pair][lane * 4 + 3];
        ((float4*)g_agg)[node * 32 + lane] = acc;

        int c = lane * 4;
        atomicAdd(&s_sum[c],     acc.x);
        atomicAdd(&s_sum[c + 1], acc.y);
        atomicAdd(&s_sum[c + 2], acc.z);
        atomicAdd(&s_sum[c + 3], acc.w);
        atomicAdd(&s_sq[c],      acc.x * acc.x);
        atomicAdd(&s_sq[c + 1],  acc.y * acc.y);
        atomicAdd(&s_sq[c + 2],  acc.z * acc.z);
        atomicAdd(&s_sq[c + 3],  acc.w * acc.w);
    }
    __syncthreads();
    if (tid < DD) {
        atomicAdd(&g_stats[soff + tid],      s_sum[tid]);
        atomicAdd(&g_stats[soff + DD + tid], s_sq[tid]);
    }
}

// ================= final BN + PReLU =================
__global__ void k_bn_out(const float* __restrict__ gamma,
                         const float* __restrict__ beta,
                         const float* __restrict__ aparam,
                         int soff, float* __restrict__ out) {
    int idx = blockIdx.x * 256 + threadIdx.x;
    if (idx >= NN * 32) return;
    int c = (idx & 31) * 4;
    float alpha = aparam[0];
    float4 v = ((const float4*)g_agg)[idx];
    float vv[4] = {v.x, v.y, v.z, v.w};
    float oo[4];
#pragma unroll
    for (int j = 0; j < 4; j++) {
        float mu  = g_stats[soff + c + j] * (1.f / NN);
        float var = g_stats[soff + DD + c + j] * (1.f / NN) - mu * mu;
        float rs  = rsqrtf(var + BN_EPS);
        float y = (vv[j] - mu) * rs * __ldg(&gamma[c + j]) + __ldg(&beta[c + j]);
        oo[j] = (y >= 0.f) ? y : alpha * y;
    }
    ((float4*)out)[idx] = make_float4(oo[0], oo[1], oo[2], oo[3]);
}

// ================= launch =================
extern "C" void kernel_launch(void* const* d_in, const int* in_sizes, int n_in,
                              void* d_out, int out_size) {
    const float* x      = (const float*)d_in[0];
    const int*   eidx   = (const int*)d_in[1];
    const float* W1     = (const float*)d_in[2];
    const float* b1     = (const float*)d_in[3];
    const float* gamma1 = (const float*)d_in[4];
    const float* beta1  = (const float*)d_in[5];
    const float* a1     = (const float*)d_in[6];
    const float* W2     = (const float*)d_in[7];
    const float* b2     = (const float*)d_in[8];
    const float* gamma2 = (const float*)d_in[9];
    const float* beta2  = (const float*)d_in[10];
    const float* a2     = (const float*)d_in[11];
    float* out = (float*)d_out;

    const int* src = eidx;
    const int* dst = eidx + NE;

    static bool s_init = false;
    static cudaStream_t s_side = nullptr;
    static cudaEvent_t ev_fork = nullptr, ev_join = nullptr;
    static unsigned short *p_w1h, *p_w1l, *p_w2h, *p_w2l;
    if (!s_init) {
        s_init = true;
        cudaGetSymbolAddress((void**)&p_w1h, g_w1h);
        cudaGetSymbolAddress((void**)&p_w1l, g_w1l);
        cudaGetSymbolAddress((void**)&p_w2h, g_w2h);
        cudaGetSymbolAddress((void**)&p_w2l, g_w2l);
        if (cudaStreamCreateWithFlags(&s_side, cudaStreamNonBlocking) == cudaSuccess) {
            if (cudaEventCreateWithFlags(&ev_fork, cudaEventDisableTiming) != cudaSuccess ||
                cudaEventCreateWithFlags(&ev_join, cudaEventDisableTiming) != cudaSuccess) {
                s_side = nullptr;
            }
        } else {
            s_side = nullptr;
        }
        cudaFuncSetAttribute(k_gemm_mma, cudaFuncAttributeMaxDynamicSharedMemorySize,
                             SMEM_MMA);
    }

    int nb_scan = (NN + 255) / 256;
    int nb_edge = (NE + 255) / 256;
    int nb_deg  = (NE / 4 + 255) / 256;
    int nb_gemm = 2 * ((NN + 127) / 128);
    int nb_agg  = (NN + 3) / 4;            // 12500, 2 warps/node
    int nb_elem = (NN * 32 + 255) / 256;

    cudaStream_t sp = s_side ? s_side : (cudaStream_t)0;

    // #1: prepack + zeroing (main)
    k_wprep<<<128, 256>>>(W1, W2);
    if (s_side) cudaEventRecord(ev_fork, 0);

    // #2: GEMM layer 1 (main)
    k_gemm_mma<<<nb_gemm, 256, SMEM_MMA>>>(x, p_w1h, p_w1l,
                                           nullptr, nullptr, nullptr, -1, 0);

    // #3-5: preprocessing (side, concurrent with GEMM-1)
    if (s_side) cudaStreamWaitEvent(s_side, ev_fork, 0);
    k_deg<<<nb_deg, 256, 0, sp>>>(dst);
    k_scan<<<nb_scan, 256, 0, sp>>>();
    k_csr<<<nb_edge, 256, 0, sp>>>(src, dst);
    if (s_side) {
        cudaEventRecord(ev_join, s_side);
        cudaStreamWaitEvent(0, ev_join, 0);
    }

    // #6: layer 1 aggregation
    k_agg<<<nb_agg, 256>>>(b1, 0);

    // #7-8: layer 2
    k_gemm_mma<<<nb_gemm, 256, SMEM_MMA>>>(nullptr, p_w2h, p_w2l,
                                           gamma1, beta1, a1, 0, 1);
    k_agg<<<nb_agg, 256>>>(b2, 2 * DD);

    // #9: final BN2 + PReLU -> output
    k_bn_out<<<nb_elem, 256>>>(gamma2, beta2, a2, 2 * DD, out);
}

// round 15
// speedup vs baseline: 1.4398x; 1.4398x over previous
#include <cuda_runtime.h>
#include <cuda_bf16.h>
#include <cuda_fp16.h>
#include <cstdint>

#define NN 50000
#define NE 800000
#define DD 128
#define BN_EPS 1e-5f
#define WSTRIDE 136
#define WTILE_BYTES (DD * WSTRIDE * 2)
#define WHALF_BYTES (64 * WSTRIDE * 2)

// ---- static device scratch ----
__device__ __align__(16) __half g_h16[NN * DD];
__device__ float g_agg[NN * DD];
__device__ int   g_deg[NN];
__device__ float g_dinv[NN];
__device__ int   g_rowstart[NN];
__device__ int   g_cursor[NN];
__device__ int4  g_nodeinfo[NN];      // (rowstart, deg, dinv_bits, 0)
__device__ uint32_t g_csre[NE];       // packed: fp16(w)<<16 | src (src < 65536)
__device__ float g_stats[4 * DD];
__device__ unsigned long long g_sstate[200];
__device__ unsigned int g_sctr;
__device__ __align__(16) unsigned short g_w1h[DD * WSTRIDE];
__device__ __align__(16) unsigned short g_w1l[DD * WSTRIDE];
__device__ __align__(16) unsigned short g_w2h[DD * WSTRIDE];
__device__ __align__(16) unsigned short g_w2l[DD * WSTRIDE];

// ================= helpers =================
__device__ __forceinline__ uint32_t smem_u32(const void* p) {
    uint32_t a;
    asm("{ .reg .u64 t; cvta.to.shared.u64 t, %1; cvt.u32.u64 %0, t; }"
        : "=r"(a) : "l"(p));
    return a;
}
__device__ __forceinline__ void ldsm4(uint32_t& r0, uint32_t& r1,
                                      uint32_t& r2, uint32_t& r3, uint32_t addr) {
    asm volatile("ldmatrix.sync.aligned.m8n8.x4.shared.b16 {%0,%1,%2,%3}, [%4];"
                 : "=r"(r0), "=r"(r1), "=r"(r2), "=r"(r3) : "r"(addr));
}
__device__ __forceinline__ void mma16816(float* c, uint32_t a0, uint32_t a1,
                                         uint32_t a2, uint32_t a3,
                                         uint32_t b0, uint32_t b1) {
    asm volatile("mma.sync.aligned.m16n8k16.row.col.f32.bf16.bf16.f32 "
                 "{%0,%1,%2,%3}, {%4,%5,%6,%7}, {%8,%9}, {%0,%1,%2,%3};"
                 : "+f"(c[0]), "+f"(c[1]), "+f"(c[2]), "+f"(c[3])
                 : "r"(a0), "r"(a1), "r"(a2), "r"(a3), "r"(b0), "r"(b1));
}
__device__ __forceinline__ unsigned short bf_hi(float x) {
    __nv_bfloat16 b = __float2bfloat16(x);
    return *reinterpret_cast<unsigned short*>(&b);
}
__device__ __forceinline__ float bf_val(unsigned short u) {
    __nv_bfloat16 b = *reinterpret_cast<__nv_bfloat16*>(&u);
    return __bfloat162float(b);
}

// ================= W prepack + per-call zeroing =================
__global__ void k_wprep(const float* __restrict__ W1, const float* __restrict__ W2) {
    int i = blockIdx.x * 256 + threadIdx.x;  // 32768 threads
    if (i < NN) g_deg[i] = 0;
    {
        int i2 = i + 32768;
        if (i2 < NN) g_deg[i2] = 0;
    }
    if (i < 4 * DD) g_stats[i] = 0.f;
    if (i < 200) g_sstate[i] = 0ULL;
    if (i == 0) g_sctr = 0u;
    if (i < 2 * DD * DD) {
        int layer = i >> 14;
        int idx = i & (DD * DD - 1);
        int k = idx >> 7, n = idx & 127;
        float w = (layer ? W2 : W1)[idx];
        unsigned short h = bf_hi(w);
        unsigned short l = bf_hi(w - bf_val(h));
        int o = n * WSTRIDE + k;
        if (layer) { g_w2h[o] = h; g_w2l[o] = l; }
        else       { g_w1h[o] = h; g_w1l[o] = l; }
    }
}

// ================= degree count =================
__global__ void k_deg(const int* __restrict__ dst) {
    int t = blockIdx.x * 256 + threadIdx.x;
    if (t * 4 < NE) {
        int4 d = ((const int4*)dst)[t];
        atomicAdd(&g_deg[d.x], 1);
        atomicAdd(&g_deg[d.y], 1);
        atomicAdd(&g_deg[d.z], 1);
        atomicAdd(&g_deg[d.w], 1);
    }
}

// ================= single-kernel decoupled-lookback scan =================
__global__ void k_scan() {
    __shared__ int wsum[8];
    __shared__ int s_bid, s_total, s_prefix;
    int tid = threadIdx.x;
    if (tid == 0) s_bid = (int)atomicAdd(&g_sctr, 1u);
    __syncthreads();
    int bid = s_bid;
    int i = bid * 256 + tid;
    int d0 = (i < NN) ? g_deg[i] : 0;
    int v = d0;
    int lane = tid & 31, wid = tid >> 5;
#pragma unroll
    for (int o = 1; o < 32; o <<= 1) {
        int n = __shfl_up_sync(0xffffffffu, v, o);
        if (lane >= o) v += n;
    }
    if (lane == 31) wsum[wid] = v;
    __syncthreads();
    if (wid == 0) {
        int s = (lane < 8) ? wsum[lane] : 0;
#pragma unroll
        for (int o = 1; o < 8; o <<= 1) {
            int n = __shfl_up_sync(0xffffffffu, s, o);
            if (lane >= o) s += n;
        }
        if (lane < 8) wsum[lane] = s;
    }
    __syncthreads();
    int off = (wid > 0) ? wsum[wid - 1] : 0;
    int incl = v + off;
    if (tid == 255) {
        s_total = incl;
        if (bid == 0) atomicExch(&g_sstate[0], (2ULL << 32) | (unsigned)incl);
        else          atomicExch(&g_sstate[bid], (1ULL << 32) | (unsigned)incl);
    }
    __syncthreads();
    if (tid == 0) {
        int pre = 0;
        if (bid > 0) {
            int j = bid - 1;
            for (;;) {
                unsigned long long s;
                do { s = atomicAdd(&g_sstate[j], 0ULL); } while ((s >> 32) == 0ULL);
                pre += (int)(s & 0xffffffffULL);
                if ((s >> 32) == 2ULL) break;
                j--;
            }
            atomicExch(&g_sstate[bid], (2ULL << 32) | (unsigned)(pre + s_total));
        }
        s_prefix = pre;
    }
    __syncthreads();
    if (i < NN) {
        int rs = s_prefix + incl - d0;
        float di = rsqrtf((float)(d0 + 1));
        g_rowstart[i] = rs;
        g_cursor[i] = rs;
        g_dinv[i] = di;
        g_nodeinfo[i] = make_int4(rs, d0, __float_as_int(di), 0);
    }
}

// ================= CSR fill: packed 4B records =================
__global__ void k_csr(const int* __restrict__ src, const int* __restrict__ dst) {
    int e = blockIdx.x * 256 + threadIdx.x;
    if (e < NE) {
        int s = src[e], d = dst[e];
        int pos = atomicAdd(&g_cursor[d], 1);
        float w = g_dinv[s] * g_dinv[d];
        unsigned short wh = __half_as_ushort(__float2half_rn(w));
        g_csre[pos] = ((uint32_t)wh << 16) | (uint32_t)s;
    }
}

// ================= bf16 mma GEMM: 128 rows x 64 cols per block =================
#define XH_OFF 0
#define XL_OFF WTILE_BYTES
#define WH_OFF (2 * WTILE_BYTES)
#define WL_OFF (2 * WTILE_BYTES + WHALF_BYTES)
#define SMEM_MMA (2 * WTILE_BYTES + 2 * WHALF_BYTES)

__global__ void __launch_bounds__(256, 2) k_gemm_mma(
        const float* __restrict__ Xin,
        const unsigned short* __restrict__ Wh, const unsigned short* __restrict__ Wl,
        const float* __restrict__ gamma, const float* __restrict__ beta,
        const float* __restrict__ aparam, int bn_off, int use_agg) {
    extern __shared__ char sm[];
    __shared__ float s_scale[DD];
    __shared__ float s_shift[DD];

    int tid = threadIdx.x;
    int wid = tid >> 5, lane = tid & 31;
    int row0 = (blockIdx.x >> 1) * 128;
    int nh = blockIdx.x & 1;
    const float* X = use_agg ? (const float*)g_agg : Xin;

    float alpha = 0.f;
    if (bn_off >= 0) {
        alpha = aparam[0];
        if (tid < DD) {
            float mu  = g_stats[bn_off + tid] * (1.f / NN);
            float var = g_stats[bn_off + DD + tid] * (1.f / NN) - mu * mu;
            float sc  = gamma[tid] * rsqrtf(var + BN_EPS);
            s_scale[tid] = sc;
            s_shift[tid] = beta[tid] - mu * sc;
        }
    }

    {
        const float4* sh = (const float4*)(Wh + nh * 64 * WSTRIDE);
        const float4* sl = (const float4*)(Wl + nh * 64 * WSTRIDE);
        float4* dh = (float4*)(sm + WH_OFF);
        float4* dl = (float4*)(sm + WL_OFF);
#pragma unroll 4
        for (int i = tid; i < WHALF_BYTES / 16; i += 256) { dh[i] = sh[i]; dl[i] = sl[i]; }
    }
    __syncthreads();

    {
        const float4* X4 = (const float4*)X;
#pragma unroll 4
        for (int i = tid; i < 128 * 32; i += 256) {
            int r = i >> 5, c = i & 31;
            int gr = row0 + r;
            float4 v = make_float4(0.f, 0.f, 0.f, 0.f);
            if (gr < NN) v = X4[gr * 32 + c];
            if (bn_off >= 0) {
                int cc = c * 4;
                float y;
                y = v.x * s_scale[cc]     + s_shift[cc];     v.x = (y >= 0.f) ? y : alpha * y;
                y = v.y * s_scale[cc + 1] + s_shift[cc + 1]; v.y = (y >= 0.f) ? y : alpha * y;
                y = v.z * s_scale[cc + 2] + s_shift[cc + 2]; v.z = (y >= 0.f) ? y : alpha * y;
                y = v.w * s_scale[cc + 3] + s_shift[cc + 3]; v.w = (y >= 0.f) ? y : alpha * y;
            }
            unsigned short h0 = bf_hi(v.x), h1 = bf_hi(v.y), h2 = bf_hi(v.z), h3 = bf_hi(v.w);
            unsigned short l0 = bf_hi(v.x - bf_val(h0));
            unsigned short l1 = bf_hi(v.y - bf_val(h1));
            unsigned short l2 = bf_hi(v.z - bf_val(h2));
            unsigned short l3 = bf_hi(v.w - bf_val(h3));
            int o = r * (WSTRIDE * 2) + c * 8;
            *(uint2*)(sm + XH_OFF + o) = make_uint2((uint32_t)h0 | ((uint32_t)h1 << 16),
                                                    (uint32_t)h2 | ((uint32_t)h3 << 16));
            *(uint2*)(sm + XL_OFF + o) = make_uint2((uint32_t)l0 | ((uint32_t)l1 << 16),
                                                    (uint32_t)l2 | ((uint32_t)l3 << 16));
        }
    }
    __syncthreads();

    int wrow0 = wid * 16;
    uint32_t base = smem_u32(sm);
    uint32_t a_h = base + XH_OFF + (wrow0 + (lane & 15)) * (WSTRIDE * 2) + (lane >> 4) * 16;
    uint32_t a_l = a_h + (XL_OFF - XH_OFF);
    uint32_t b_h = base + WH_OFF + ((lane >> 4) * 8 + (lane & 7)) * (WSTRIDE * 2)
                 + ((lane >> 3) & 1) * 16;
    uint32_t b_l = b_h + (WL_OFF - WH_OFF);

    float acc[8][4];
#pragma unroll
    for (int nt = 0; nt < 8; nt++)
#pragma unroll
        for (int j = 0; j < 4; j++) acc[nt][j] = 0.f;

#pragma unroll 1
    for (int p = 0; p < 3; p++) {
        uint32_t aa = (p == 2) ? a_l : a_h;
        uint32_t bb = (p == 1) ? b_l : b_h;
#pragma unroll 1
        for (int k = 0; k < 8; k++) {
            uint32_t a0, a1, a2, a3;
            ldsm4(a0, a1, a2, a3, aa + k * 32);
#pragma unroll
            for (int ntp = 0; ntp < 4; ntp++) {
                uint32_t b0, b1, b2, b3;
                ldsm4(b0, b1, b2, b3, bb + k * 32 + ntp * 16 * (WSTRIDE * 2));
                mma16816(acc[2 * ntp],     a0, a1, a2, a3, b0, b1);
                mma16816(acc[2 * ntp + 1], a0, a1, a2, a3, b2, b3);
            }
        }
    }

    int g = lane >> 2, t = lane & 3;
    int r1 = row0 + wrow0 + g;
    int r2 = r1 + 8;
#pragma unroll
    for (int nt = 0; nt < 8; nt++) {
        int col = nh * 64 + nt * 8 + t * 2;
        if (r1 < NN)
            *(__half2*)(g_h16 + (size_t)r1 * DD + col) =
                __floats2half2_rn(acc[nt][0], acc[nt][1]);
        if (r2 < NN)
            *(__half2*)(g_h16 + (size_t)r2 * DD + col) =
                __floats2half2_rn(acc[nt][2], acc[nt][3]);
    }
}

// ================= CSR aggregation: 8-wide prefetch + masked tail, 4B edges =================
__global__ void k_agg(const float* __restrict__ bias, int soff) {
    __shared__ float s_sum[DD];
    __shared__ float s_sq[DD];
    int tid = threadIdx.x;
    if (tid < DD) { s_sum[tid] = 0.f; s_sq[tid] = 0.f; }
    __syncthreads();

    int node = blockIdx.x * 8 + (tid >> 5);
    int lane = tid & 31;
    if (node < NN) {
        const uint2* h2 = (const uint2*)g_h16;
        int4 ni = __ldg(&g_nodeinfo[node]);
        int base = ni.x;
        int cnt  = ni.y;
        float di = __int_as_float(ni.z);
        float w0 = di * di;
        uint2 sr = __ldg(&h2[node * 32 + lane]);
        float2 s01 = __half22float2(*(__half2*)&sr.x);
        float2 s23 = __half22float2(*(__half2*)&sr.y);
        float4 bv = __ldg(&((const float4*)bias)[lane]);
        float4 acc;
        acc.x = s01.x * w0 + bv.x;
        acc.y = s01.y * w0 + bv.y;
        acc.z = s23.x * w0 + bv.z;
        acc.w = s23.y * w0 + bv.w;

        const uint32_t* ep = g_csre + base;
        int ngr = (cnt + 7) >> 3;   // groups incl. masked tail
        if (ngr > 0) {
            uint32_t e[8];
#pragma unroll
            for (int u = 0; u < 8; u++)
                e[u] = (u < cnt) ? __ldg(ep + u) : (uint32_t)node;  // w bits=0 -> w=0
#pragma unroll 1
            for (int grp = 1; grp <= ngr; grp++) {
                uint2 r[8];
#pragma unroll
                for (int u = 0; u < 8; u++)
                    r[u] = __ldg(&h2[(e[u] & 0xFFFFu) * 32 + lane]);
                float w[8];
#pragma unroll
                for (int u = 0; u < 8; u++)
                    w[u] = __half2float(__ushort_as_half((unsigned short)(e[u] >> 16)));
                if (grp < ngr) {
                    int j0 = grp * 8;
#pragma unroll
                    for (int u = 0; u < 8; u++)
                        e[u] = (j0 + u < cnt) ? __ldg(ep + j0 + u) : (uint32_t)node;
                }
#pragma unroll
                for (int u = 0; u < 8; u++) {
                    float2 f01 = __half22float2(*(__half2*)&r[u].x);
                    float2 f23 = __half22float2(*(__half2*)&r[u].y);
                    acc.x += f01.x * w[u];
                    acc.y += f01.y * w[u];
                    acc.z += f23.x * w[u];
                    acc.w += f23.y * w[u];
                }
            }
        }
        ((float4*)g_agg)[node * 32 + lane] = acc;

        int c = lane * 4;
        atomicAdd(&s_sum[c],     acc.x);
        atomicAdd(&s_sum[c + 1], acc.y);
        atomicAdd(&s_sum[c + 2], acc.z);
        atomicAdd(&s_sum[c + 3], acc.w);
        atomicAdd(&s_sq[c],      acc.x * acc.x);
        atomicAdd(&s_sq[c + 1],  acc.y * acc.y);
        atomicAdd(&s_sq[c + 2],  acc.z * acc.z);
        atomicAdd(&s_sq[c + 3],  acc.w * acc.w);
    }
    __syncthreads();
    if (tid < DD) {
        atomicAdd(&g_stats[soff + tid],      s_sum[tid]);
        atomicAdd(&g_stats[soff + DD + tid], s_sq[tid]);
    }
}

// ================= final BN + PReLU =================
__global__ void k_bn_out(const float* __restrict__ gamma,
                         const float* __restrict__ beta,
                         const float* __restrict__ aparam,
                         int soff, float* __restrict__ out) {
    int idx = blockIdx.x * 256 + threadIdx.x;
    if (idx >= NN * 32) return;
    int c = (idx & 31) * 4;
    float alpha = aparam[0];
    float4 v = ((const float4*)g_agg)[idx];
    float vv[4] = {v.x, v.y, v.z, v.w};
    float oo[4];
#pragma unroll
    for (int j = 0; j < 4; j++) {
        float mu  = g_stats[soff + c + j] * (1.f / NN);
        float var = g_stats[soff + DD + c + j] * (1.f / NN) - mu * mu;
        float rs  = rsqrtf(var + BN_EPS);
        float y = (vv[j] - mu) * rs * __ldg(&gamma[c + j]) + __ldg(&beta[c + j]);
        oo[j] = (y >= 0.f) ? y : alpha * y;
    }
    ((float4*)out)[idx] = make_float4(oo[0], oo[1], oo[2], oo[3]);
}

// ================= launch =================
extern "C" void kernel_launch(void* const* d_in, const int* in_sizes, int n_in,
                              void* d_out, int out_size) {
    const float* x      = (const float*)d_in[0];
    const int*   eidx   = (const int*)d_in[1];
    const float* W1     = (const float*)d_in[2];
    const float* b1     = (const float*)d_in[3];
    const float* gamma1 = (const float*)d_in[4];
    const float* beta1  = (const float*)d_in[5];
    const float* a1     = (const float*)d_in[6];
    const float* W2     = (const float*)d_in[7];
    const float* b2     = (const float*)d_in[8];
    const float* gamma2 = (const float*)d_in[9];
    const float* beta2  = (const float*)d_in[10];
    const float* a2     = (const float*)d_in[11];
    float* out = (float*)d_out;

    const int* src = eidx;
    const int* dst = eidx + NE;

    static bool s_init = false;
    static cudaStream_t s_side = nullptr;
    static cudaEvent_t ev_fork = nullptr, ev_join = nullptr;
    static unsigned short *p_w1h, *p_w1l, *p_w2h, *p_w2l;
    if (!s_init) {
        s_init = true;
        cudaGetSymbolAddress((void**)&p_w1h, g_w1h);
        cudaGetSymbolAddress((void**)&p_w1l, g_w1l);
        cudaGetSymbolAddress((void**)&p_w2h, g_w2h);
        cudaGetSymbolAddress((void**)&p_w2l, g_w2l);
        if (cudaStreamCreateWithFlags(&s_side, cudaStreamNonBlocking) == cudaSuccess) {
            if (cudaEventCreateWithFlags(&ev_fork, cudaEventDisableTiming) != cudaSuccess ||
                cudaEventCreateWithFlags(&ev_join, cudaEventDisableTiming) != cudaSuccess) {
                s_side = nullptr;
            }
        } else {
            s_side = nullptr;
        }
        cudaFuncSetAttribute(k_gemm_mma, cudaFuncAttributeMaxDynamicSharedMemorySize,
                             SMEM_MMA);
    }

    int nb_scan = (NN + 255) / 256;
    int nb_edge = (NE + 255) / 256;
    int nb_deg  = (NE / 4 + 255) / 256;
    int nb_gemm = 2 * ((NN + 127) / 128);
    int nb_agg  = (NN + 7) / 8;
    int nb_elem = (NN * 32 + 255) / 256;

    cudaStream_t sp = s_side ? s_side : (cudaStream_t)0;

    // #1: prepack + zeroing (main)
    k_wprep<<<128, 256>>>(W1, W2);
    if (s_side) cudaEventRecord(ev_fork, 0);

    // #2: GEMM layer 1 (main)
    k_gemm_mma<<<nb_gemm, 256, SMEM_MMA>>>(x, p_w1h, p_w1l,
                                           nullptr, nullptr, nullptr, -1, 0);

    // #3-5: preprocessing (side, concurrent with GEMM-1)
    if (s_side) cudaStreamWaitEvent(s_side, ev_fork, 0);
    k_deg<<<nb_deg, 256, 0, sp>>>(dst);
    k_scan<<<nb_scan, 256, 0, sp>>>();
    k_csr<<<nb_edge, 256, 0, sp>>>(src, dst);
    if (s_side) {
        cudaEventRecord(ev_join, s_side);
        cudaStreamWaitEvent(0, ev_join, 0);
    }

    // #6: layer 1 aggregation
    k_agg<<<nb_agg, 256>>>(b1, 0);

    // #7-8: layer 2
    k_gemm_mma<<<nb_gemm, 256, SMEM_MMA>>>(nullptr, p_w2h, p_w2l,
                                           gamma1, beta1, a1, 0, 1);
    k_agg<<<nb_agg, 256>>>(b2, 2 * DD);

    // #9: final BN2 + PReLU -> output
    k_bn_out<<<nb_elem, 256>>>(gamma2, beta2, a2, 2 * DD, out);
}

// round 16
// speedup vs baseline: 1.9891x; 1.3815x over previous
#include <cuda_runtime.h>
#include <cuda_bf16.h>
#include <cuda_fp16.h>
#include <cstdint>

#define NN 50000
#define NE 800000
#define DD 128
#define BN_EPS 1e-5f
#define WSTRIDE 136
#define WTILE_BYTES (DD * WSTRIDE * 2)
#define WHALF_BYTES (64 * WSTRIDE * 2)
#define NROWTILES ((NN + 127) / 128)   // 391
#define GEMM_BLOCKS 296                // 2/SM x 148

// ---- static device scratch ----
__device__ __align__(16) __half g_h16[NN * DD];
__device__ float g_agg[NN * DD];
__device__ int   g_deg[NN];
__device__ float g_dinv[NN];
__device__ int   g_rowstart[NN];
__device__ int   g_cursor[NN];
__device__ int4  g_nodeinfo[NN];      // (rowstart, deg, dinv_bits, 0)
__device__ uint32_t g_csre[NE];       // packed: fp16(w)<<16 | src
__device__ float g_stats[4 * DD];
__device__ unsigned long long g_sstate[200];
__device__ unsigned int g_sctr;
__device__ __align__(16) unsigned short g_w1h[DD * WSTRIDE];
__device__ __align__(16) unsigned short g_w1l[DD * WSTRIDE];
__device__ __align__(16) unsigned short g_w2h[DD * WSTRIDE];
__device__ __align__(16) unsigned short g_w2l[DD * WSTRIDE];

// ================= helpers =================
__device__ __forceinline__ uint32_t smem_u32(const void* p) {
    uint32_t a;
    asm("{ .reg .u64 t; cvta.to.shared.u64 t, %1; cvt.u32.u64 %0, t; }"
        : "=r"(a) : "l"(p));
    return a;
}
__device__ __forceinline__ void ldsm4(uint32_t& r0, uint32_t& r1,
                                      uint32_t& r2, uint32_t& r3, uint32_t addr) {
    asm volatile("ldmatrix.sync.aligned.m8n8.x4.shared.b16 {%0,%1,%2,%3}, [%4];"
                 : "=r"(r0), "=r"(r1), "=r"(r2), "=r"(r3) : "r"(addr));
}
__device__ __forceinline__ void mma16816(float* c, uint32_t a0, uint32_t a1,
                                         uint32_t a2, uint32_t a3,
                                         uint32_t b0, uint32_t b1) {
    asm volatile("mma.sync.aligned.m16n8k16.row.col.f32.bf16.bf16.f32 "
                 "{%0,%1,%2,%3}, {%4,%5,%6,%7}, {%8,%9}, {%0,%1,%2,%3};"
                 : "+f"(c[0]), "+f"(c[1]), "+f"(c[2]), "+f"(c[3])
                 : "r"(a0), "r"(a1), "r"(a2), "r"(a3), "r"(b0), "r"(b1));
}
__device__ __forceinline__ unsigned short bf_hi(float x) {
    __nv_bfloat16 b = __float2bfloat16(x);
    return *reinterpret_cast<unsigned short*>(&b);
}
__device__ __forceinline__ float bf_val(unsigned short u) {
    __nv_bfloat16 b = *reinterpret_cast<__nv_bfloat16*>(&u);
    return __bfloat162float(b);
}

// ================= W prepack + per-call zeroing =================
__global__ void k_wprep(const float* __restrict__ W1, const float* __restrict__ W2) {
    int i = blockIdx.x * 256 + threadIdx.x;  // 32768 threads
    if (i < NN) g_deg[i] = 0;
    {
        int i2 = i + 32768;
        if (i2 < NN) g_deg[i2] = 0;
    }
    if (i < 4 * DD) g_stats[i] = 0.f;
    if (i < 200) g_sstate[i] = 0ULL;
    if (i == 0) g_sctr = 0u;
    if (i < 2 * DD * DD) {
        int layer = i >> 14;
        int idx = i & (DD * DD - 1);
        int k = idx >> 7, n = idx & 127;
        float w = (layer ? W2 : W1)[idx];
        unsigned short h = bf_hi(w);
        unsigned short l = bf_hi(w - bf_val(h));
        int o = n * WSTRIDE + k;
        if (layer) { g_w2h[o] = h; g_w2l[o] = l; }
        else       { g_w1h[o] = h; g_w1l[o] = l; }
    }
}

// ================= degree count =================
__global__ void k_deg(const int* __restrict__ dst) {
    int t = blockIdx.x * 256 + threadIdx.x;
    if (t * 4 < NE) {
        int4 d = ((const int4*)dst)[t];
        atomicAdd(&g_deg[d.x], 1);
        atomicAdd(&g_deg[d.y], 1);
        atomicAdd(&g_deg[d.z], 1);
        atomicAdd(&g_deg[d.w], 1);
    }
}

// ================= single-kernel decoupled-lookback scan =================
__global__ void k_scan() {
    __shared__ int wsum[8];
    __shared__ int s_bid, s_total, s_prefix;
    int tid = threadIdx.x;
    if (tid == 0) s_bid = (int)atomicAdd(&g_sctr, 1u);
    __syncthreads();
    int bid = s_bid;
    int i = bid * 256 + tid;
    int d0 = (i < NN) ? g_deg[i] : 0;
    int v = d0;
    int lane = tid & 31, wid = tid >> 5;
#pragma unroll
    for (int o = 1; o < 32; o <<= 1) {
        int n = __shfl_up_sync(0xffffffffu, v, o);
        if (lane >= o) v += n;
    }
    if (lane == 31) wsum[wid] = v;
    __syncthreads();
    if (wid == 0) {
        int s = (lane < 8) ? wsum[lane] : 0;
#pragma unroll
        for (int o = 1; o < 8; o <<= 1) {
            int n = __shfl_up_sync(0xffffffffu, s, o);
            if (lane >= o) s += n;
        }
        if (lane < 8) wsum[lane] = s;
    }
    __syncthreads();
    int off = (wid > 0) ? wsum[wid - 1] : 0;
    int incl = v + off;
    if (tid == 255) {
        s_total = incl;
        if (bid == 0) atomicExch(&g_sstate[0], (2ULL << 32) | (unsigned)incl);
        else          atomicExch(&g_sstate[bid], (1ULL << 32) | (unsigned)incl);
    }
    __syncthreads();
    if (tid == 0) {
        int pre = 0;
        if (bid > 0) {
            int j = bid - 1;
            for (;;) {
                unsigned long long s;
                do { s = atomicAdd(&g_sstate[j], 0ULL); } while ((s >> 32) == 0ULL);
                pre += (int)(s & 0xffffffffULL);
                if ((s >> 32) == 2ULL) break;
                j--;
            }
            atomicExch(&g_sstate[bid], (2ULL << 32) | (unsigned)(pre + s_total));
        }
        s_prefix = pre;
    }
    __syncthreads();
    if (i < NN) {
        int rs = s_prefix + incl - d0;
        float di = rsqrtf((float)(d0 + 1));
        g_rowstart[i] = rs;
        g_cursor[i] = rs;
        g_dinv[i] = di;
        g_nodeinfo[i] = make_int4(rs, d0, __float_as_int(di), 0);
    }
}

// ================= CSR fill: packed 4B records =================
__global__ void k_csr(const int* __restrict__ src, const int* __restrict__ dst) {
    int e = blockIdx.x * 256 + threadIdx.x;
    if (e < NE) {
        int s = src[e], d = dst[e];
        int pos = atomicAdd(&g_cursor[d], 1);
        float w = g_dinv[s] * g_dinv[d];
        unsigned short wh = __half_as_ushort(__float2half_rn(w));
        g_csre[pos] = ((uint32_t)wh << 16) | (uint32_t)s;
    }
}

// ================= persistent-W bf16 mma GEMM =================
// grid = 296: blocks 0-147 -> n-half 0, 148-295 -> n-half 1.
// Each block copies its W half ONCE, then loops row tiles (stride 148).
#define XH_OFF 0
#define XL_OFF WTILE_BYTES
#define WH_OFF (2 * WTILE_BYTES)
#define WL_OFF (2 * WTILE_BYTES + WHALF_BYTES)
#define SMEM_MMA (2 * WTILE_BYTES + 2 * WHALF_BYTES)

__global__ void __launch_bounds__(256, 2) k_gemm_mma(
        const float* __restrict__ Xin,
        const unsigned short* __restrict__ Wh, const unsigned short* __restrict__ Wl,
        const float* __restrict__ gamma, const float* __restrict__ beta,
        const float* __restrict__ aparam, int bn_off, int use_agg) {
    extern __shared__ char sm[];
    __shared__ float s_scale[DD];
    __shared__ float s_shift[DD];

    int tid = threadIdx.x;
    int wid = tid >> 5, lane = tid & 31;
    int nh = (blockIdx.x >= 148) ? 1 : 0;
    int rb = blockIdx.x - nh * 148;
    const float* X = use_agg ? (const float*)g_agg : Xin;

    float alpha = 0.f;
    if (bn_off >= 0) {
        alpha = aparam[0];
        if (tid < DD) {
            float mu  = g_stats[bn_off + tid] * (1.f / NN);
            float var = g_stats[bn_off + DD + tid] * (1.f / NN) - mu * mu;
            float sc  = gamma[tid] * rsqrtf(var + BN_EPS);
            s_scale[tid] = sc;
            s_shift[tid] = beta[tid] - mu * sc;
        }
    }

    // copy this block's W half once
    {
        const float4* sh = (const float4*)(Wh + nh * 64 * WSTRIDE);
        const float4* sl = (const float4*)(Wl + nh * 64 * WSTRIDE);
        float4* dh = (float4*)(sm + WH_OFF);
        float4* dl = (float4*)(sm + WL_OFF);
#pragma unroll 4
        for (int i = tid; i < WHALF_BYTES / 16; i += 256) { dh[i] = sh[i]; dl[i] = sl[i]; }
    }

    // fragment addresses (row0-independent)
    int wrow0 = wid * 16;
    uint32_t base = smem_u32(sm);
    uint32_t a_h = base + XH_OFF + (wrow0 + (lane & 15)) * (WSTRIDE * 2) + (lane >> 4) * 16;
    uint32_t a_l = a_h + (XL_OFF - XH_OFF);
    uint32_t b_h = base + WH_OFF + ((lane >> 4) * 8 + (lane & 7)) * (WSTRIDE * 2)
                 + ((lane >> 3) & 1) * 16;
    uint32_t b_l = b_h + (WL_OFF - WH_OFF);

    const float4* X4 = (const float4*)X;

#pragma unroll 1
    for (int rt = rb; rt < NROWTILES; rt += 148) {
        int row0 = rt * 128;
        __syncthreads();  // W + s_scale ready (iter 1); X consumers done (iter>1)

        // load X tile, optional BN+PReLU, split hi/lo
#pragma unroll 4
        for (int i = tid; i < 128 * 32; i += 256) {
            int r = i >> 5, c = i & 31;
            int gr = row0 + r;
            float4 v = make_float4(0.f, 0.f, 0.f, 0.f);
            if (gr < NN) v = X4[gr * 32 + c];
            if (bn_off >= 0) {
                int cc = c * 4;
                float y;
                y = v.x * s_scale[cc]     + s_shift[cc];     v.x = (y >= 0.f) ? y : alpha * y;
                y = v.y * s_scale[cc + 1] + s_shift[cc + 1]; v.y = (y >= 0.f) ? y : alpha * y;
                y = v.z * s_scale[cc + 2] + s_shift[cc + 2]; v.z = (y >= 0.f) ? y : alpha * y;
                y = v.w * s_scale[cc + 3] + s_shift[cc + 3]; v.w = (y >= 0.f) ? y : alpha * y;
            }
            unsigned short h0 = bf_hi(v.x), h1 = bf_hi(v.y), h2 = bf_hi(v.z), h3 = bf_hi(v.w);
            unsigned short l0 = bf_hi(v.x - bf_val(h0));
            unsigned short l1 = bf_hi(v.y - bf_val(h1));
            unsigned short l2 = bf_hi(v.z - bf_val(h2));
            unsigned short l3 = bf_hi(v.w - bf_val(h3));
            int o = r * (WSTRIDE * 2) + c * 8;
            *(uint2*)(sm + XH_OFF + o) = make_uint2((uint32_t)h0 | ((uint32_t)h1 << 16),
                                                    (uint32_t)h2 | ((uint32_t)h3 << 16));
            *(uint2*)(sm + XL_OFF + o) = make_uint2((uint32_t)l0 | ((uint32_t)l1 << 16),
                                                    (uint32_t)l2 | ((uint32_t)l3 << 16));
        }
        __syncthreads();

        float acc[8][4];
#pragma unroll
        for (int nt = 0; nt < 8; nt++)
#pragma unroll
            for (int j = 0; j < 4; j++) acc[nt][j] = 0.f;

#pragma unroll 1
        for (int p = 0; p < 3; p++) {
            uint32_t aa = (p == 2) ? a_l : a_h;
            uint32_t bb = (p == 1) ? b_l : b_h;
#pragma unroll 1
            for (int k = 0; k < 8; k++) {
                uint32_t a0, a1, a2, a3;
                ldsm4(a0, a1, a2, a3, aa + k * 32);
#pragma unroll
                for (int ntp = 0; ntp < 4; ntp++) {
                    uint32_t b0, b1, b2, b3;
                    ldsm4(b0, b1, b2, b3, bb + k * 32 + ntp * 16 * (WSTRIDE * 2));
                    mma16816(acc[2 * ntp],     a0, a1, a2, a3, b0, b1);
                    mma16816(acc[2 * ntp + 1], a0, a1, a2, a3, b2, b3);
                }
            }
        }

        int g = lane >> 2, t = lane & 3;
        int r1 = row0 + wrow0 + g;
        int r2 = r1 + 8;
#pragma unroll
        for (int nt = 0; nt < 8; nt++) {
            int col = nh * 64 + nt * 8 + t * 2;
            if (r1 < NN)
                *(__half2*)(g_h16 + (size_t)r1 * DD + col) =
                    __floats2half2_rn(acc[nt][0], acc[nt][1]);
            if (r2 < NN)
                *(__half2*)(g_h16 + (size_t)r2 * DD + col) =
                    __floats2half2_rn(acc[nt][2], acc[nt][3]);
        }
    }
}

// ================= CSR aggregation: grid-stride, 64 nodes/block =================
// stats accumulate in registers across 8 chunks, one flush per block.
__global__ void k_agg(const float* __restrict__ bias, int soff) {
    __shared__ float s_sum[DD];
    __shared__ float s_sq[DD];
    int tid = threadIdx.x;
    if (tid < DD) { s_sum[tid] = 0.f; s_sq[tid] = 0.f; }
    __syncthreads();

    int wid = tid >> 5, lane = tid & 31;
    const uint2* h2 = (const uint2*)g_h16;
    float4 bv = __ldg(&((const float4*)bias)[lane]);
    float ls0 = 0.f, ls1 = 0.f, ls2 = 0.f, ls3 = 0.f;
    float lq0 = 0.f, lq1 = 0.f, lq2 = 0.f, lq3 = 0.f;

#pragma unroll 1
    for (int it = 0; it < 8; it++) {
        int node = blockIdx.x * 64 + it * 8 + wid;
        if (node >= NN) break;
        int4 ni = __ldg(&g_nodeinfo[node]);
        int base = ni.x;
        int cnt  = ni.y;
        float di = __int_as_float(ni.z);
        float w0 = di * di;
        uint2 sr = __ldg(&h2[node * 32 + lane]);
        float2 s01 = __half22float2(*(__half2*)&sr.x);
        float2 s23 = __half22float2(*(__half2*)&sr.y);
        float4 acc;
        acc.x = s01.x * w0 + bv.x;
        acc.y = s01.y * w0 + bv.y;
        acc.z = s23.x * w0 + bv.z;
        acc.w = s23.y * w0 + bv.w;

        const uint32_t* ep = g_csre + base;
        int ngr = (cnt + 7) >> 3;
        if (ngr > 0) {
            uint32_t e[8];
#pragma unroll
            for (int u = 0; u < 8; u++)
                e[u] = (u < cnt) ? __ldg(ep + u) : (uint32_t)node;
#pragma unroll 1
            for (int grp = 1; grp <= ngr; grp++) {
                uint2 r[8];
#pragma unroll
                for (int u = 0; u < 8; u++)
                    r[u] = __ldg(&h2[(e[u] & 0xFFFFu) * 32 + lane]);
                float w[8];
#pragma unroll
                for (int u = 0; u < 8; u++)
                    w[u] = __half2float(__ushort_as_half((unsigned short)(e[u] >> 16)));
                if (grp < ngr) {
                    int j0 = grp * 8;
#pragma unroll
                    for (int u = 0; u < 8; u++)
                        e[u] = (j0 + u < cnt) ? __ldg(ep + j0 + u) : (uint32_t)node;
                }
#pragma unroll
                for (int u = 0; u < 8; u++) {
                    float2 f01 = __half22float2(*(__half2*)&r[u].x);
                    float2 f23 = __half22float2(*(__half2*)&r[u].y);
                    acc.x += f01.x * w[u];
                    acc.y += f01.y * w[u];
                    acc.z += f23.x * w[u];
                    acc.w += f23.y * w[u];
                }
            }
        }
        ((float4*)g_agg)[node * 32 + lane] = acc;

        ls0 += acc.x; ls1 += acc.y; ls2 += acc.z; ls3 += acc.w;
        lq0 += acc.x * acc.x; lq1 += acc.y * acc.y;
        lq2 += acc.z * acc.z; lq3 += acc.w * acc.w;
    }

    int c = lane * 4;
    atomicAdd(&s_sum[c],     ls0);
    atomicAdd(&s_sum[c + 1], ls1);
    atomicAdd(&s_sum[c + 2], ls2);
    atomicAdd(&s_sum[c + 3], ls3);
    atomicAdd(&s_sq[c],      lq0);
    atomicAdd(&s_sq[c + 1],  lq1);
    atomicAdd(&s_sq[c + 2],  lq2);
    atomicAdd(&s_sq[c + 3],  lq3);
    __syncthreads();
    if (tid < DD) {
        atomicAdd(&g_stats[soff + tid],      s_sum[tid]);
        atomicAdd(&g_stats[soff + DD + tid], s_sq[tid]);
    }
}

// ================= final BN + PReLU =================
__global__ void k_bn_out(const float* __restrict__ gamma,
                         const float* __restrict__ beta,
                         const float* __restrict__ aparam,
                         int soff, float* __restrict__ out) {
    int idx = blockIdx.x * 256 + threadIdx.x;
    if (idx >= NN * 32) return;
    int c = (idx & 31) * 4;
    float alpha = aparam[0];
    float4 v = ((const float4*)g_agg)[idx];
    float vv[4] = {v.x, v.y, v.z, v.w};
    float oo[4];
#pragma unroll
    for (int j = 0; j < 4; j++) {
        float mu  = g_stats[soff + c + j] * (1.f / NN);
        float var = g_stats[soff + DD + c + j] * (1.f / NN) - mu * mu;
        float rs  = rsqrtf(var + BN_EPS);
        float y = (vv[j] - mu) * rs * __ldg(&gamma[c + j]) + __ldg(&beta[c + j]);
        oo[j] = (y >= 0.f) ? y : alpha * y;
    }
    ((float4*)out)[idx] = make_float4(oo[0], oo[1], oo[2], oo[3]);
}

// ================= launch =================
extern "C" void kernel_launch(void* const* d_in, const int* in_sizes, int n_in,
                              void* d_out, int out_size) {
    const float* x      = (const float*)d_in[0];
    const int*   eidx   = (const int*)d_in[1];
    const float* W1     = (const float*)d_in[2];
    const float* b1     = (const float*)d_in[3];
    const float* gamma1 = (const float*)d_in[4];
    const float* beta1  = (const float*)d_in[5];
    const float* a1     = (const float*)d_in[6];
    const float* W2     = (const float*)d_in[7];
    const float* b2     = (const float*)d_in[8];
    const float* gamma2 = (const float*)d_in[9];
    const float* beta2  = (const float*)d_in[10];
    const float* a2     = (const float*)d_in[11];
    float* out = (float*)d_out;

    const int* src = eidx;
    const int* dst = eidx + NE;

    static bool s_init = false;
    static cudaStream_t s_side = nullptr;
    static cudaEvent_t ev_fork = nullptr, ev_join = nullptr;
    static unsigned short *p_w1h, *p_w1l, *p_w2h, *p_w2l;
    if (!s_init) {
        s_init = true;
        cudaGetSymbolAddress((void**)&p_w1h, g_w1h);
        cudaGetSymbolAddress((void**)&p_w1l, g_w1l);
        cudaGetSymbolAddress((void**)&p_w2h, g_w2h);
        cudaGetSymbolAddress((void**)&p_w2l, g_w2l);
        if (cudaStreamCreateWithFlags(&s_side, cudaStreamNonBlocking) == cudaSuccess) {
            if (cudaEventCreateWithFlags(&ev_fork, cudaEventDisableTiming) != cudaSuccess ||
                cudaEventCreateWithFlags(&ev_join, cudaEventDisableTiming) != cudaSuccess) {
                s_side = nullptr;
            }
        } else {
            s_side = nullptr;
        }
        cudaFuncSetAttribute(k_gemm_mma, cudaFuncAttributeMaxDynamicSharedMemorySize,
                             SMEM_MMA);
    }

    int nb_scan = (NN + 255) / 256;
    int nb_edge = (NE + 255) / 256;
    int nb_deg  = (NE / 4 + 255) / 256;
    int nb_agg  = (NN + 63) / 64;          // 782
    int nb_elem = (NN * 32 + 255) / 256;

    cudaStream_t sp = s_side ? s_side : (cudaStream_t)0;

    // #1: prepack + zeroing (main)
    k_wprep<<<128, 256>>>(W1, W2);
    if (s_side) cudaEventRecord(ev_fork, 0);

    // #2: GEMM layer 1 (main)
    k_gemm_mma<<<GEMM_BLOCKS, 256, SMEM_MMA>>>(x, p_w1h, p_w1l,
                                               nullptr, nullptr, nullptr, -1, 0);

    // #3-5: preprocessing (side, concurrent with GEMM-1)
    if (s_side) cudaStreamWaitEvent(s_side, ev_fork, 0);
    k_deg<<<nb_deg, 256, 0, sp>>>(dst);
    k_scan<<<nb_scan, 256, 0, sp>>>();
    k_csr<<<nb_edge, 256, 0, sp>>>(src, dst);
    if (s_side) {
        cudaEventRecord(ev_join, s_side);
        cudaStreamWaitEvent(0, ev_join, 0);
    }

    // #6: layer 1 aggregation
    k_agg<<<nb_agg, 256>>>(b1, 0);

    // #7-8: layer 2
    k_gemm_mma<<<GEMM_BLOCKS, 256, SMEM_MMA>>>(nullptr, p_w2h, p_w2l,
                                               gamma1, beta1, a1, 0, 1);
    k_agg<<<nb_agg, 256>>>(b2, 2 * DD);

    // #9: final BN2 + PReLU -> output
    k_bn_out<<<nb_elem, 256>>>(gamma2, beta2, a2, 2 * DD, out);
}